// round 12
// baseline (speedup 1.0000x reference)
#include <cuda_runtime.h>
#include <cuda_fp16.h>
#include <cstdint>

// ---------------- problem constants ----------------
#define BATCH   2048
#define RDIM    256
#define HIDD    256
#define CONDD   128
#define ZCD     384
#define NCHD    64
#define MAXLEN  128
#define NBLK    128            // 32 M-tiles x 4 N-quarters
#define NT      512            // 16 warps: (4 m-tiles) x (4 n-groups)
#define MROWS   64             // batch rows per CTA (quartet shares them)
#define NTILES  34             // n8 tiles per CTA: 32 gate (64 hcols x 4) + 2 logit
#define KTILES  16
#define APITCH  264            // u16 pitch of A planes (conflict-free)

#define W_U4    (NTILES*8*32)          // 8704 uint4 = 139264 B (kt-paired layout)
// dynamic smem layout (bytes)
#define OFF_W    0
#define OFF_AHI  139264
#define OFF_ALO  (OFF_AHI + MROWS*APITCH*2)   // +33792
#define OFF_HS   (OFF_ALO + MROWS*APITCH*2)   // +33792
#define OFF_BIAS (OFF_HS + MROWS*64*4)        // +16384
#define SMEM_DYN (OFF_BIAS + 1536)            // 224768

// ---------------- device-global scratch ----------------
__device__ __align__(16) uint4 g_bs[4 * W_U4];            // per-quarter W fragments (kt-paired)
__device__ float    g_h1[BATCH * RDIM];
__device__ uint32_t g_stage[32 * 4 * 2 * (MROWS * 64)];    // [m][q][parity][row*64+hc] = 4MB
__device__ int      g_flag[128];
__device__ float    g_WhhT[RDIM * 768];
__device__ float    g_WlhT[ZCD * RDIM];

// ---------------- helpers ----------------
__device__ __forceinline__ float sigf(float x) { return 1.0f / (1.0f + __expf(-x)); }
__device__ __forceinline__ float tanha(float x) {
    float y; asm("tanh.approx.f32 %0, %1;" : "=f"(y) : "f"(x)); return y;
}
__device__ __forceinline__ uint16_t h_hi(float x) {
    __half h = __float2half_rn(x); return __half_as_ushort(h);
}
__device__ __forceinline__ uint16_t h_lo(float x) {
    __half h = __float2half_rn(x);
    return __half_as_ushort(__float2half_rn(x - __half2float(h)));
}
__device__ __forceinline__ uint32_t smem_u32(const void* p) {
    uint32_t a;
    asm("{ .reg .u64 t; cvta.to.shared.u64 t, %1; cvt.u32.u64 %0, t; }" : "=r"(a) : "l"(p));
    return a;
}
__device__ __forceinline__ void flag_release(int* p, int v) {
    asm volatile("st.release.gpu.s32 [%0], %1;" :: "l"(p), "r"(v) : "memory");
}
__device__ __forceinline__ int flag_acquire(const int* p) {
    int v; asm volatile("ld.acquire.gpu.s32 %0, [%1];" : "=r"(v) : "l"(p) : "memory");
    return v;
}
__device__ __forceinline__ float2 ffma2(float2 a, float2 b, float2 c) {
    unsigned long long au = *reinterpret_cast<unsigned long long*>(&a);
    unsigned long long bu = *reinterpret_cast<unsigned long long*>(&b);
    unsigned long long cu = *reinterpret_cast<unsigned long long*>(&c);
    unsigned long long du;
    asm("fma.rn.f32x2 %0, %1, %2, %3;" : "=l"(du) : "l"(au), "l"(bu), "l"(cu));
    return *reinterpret_cast<float2*>(&du);
}
__device__ __forceinline__ void mma16816(float* d, uint32_t a0, uint32_t a1, uint32_t a2, uint32_t a3,
                                         uint32_t b0, uint32_t b1) {
    asm volatile(
        "mma.sync.aligned.m16n8k16.row.col.f32.f16.f16.f32 "
        "{%0,%1,%2,%3}, {%4,%5,%6,%7}, {%8,%9}, {%0,%1,%2,%3};"
        : "+f"(d[0]), "+f"(d[1]), "+f"(d[2]), "+f"(d[3])
        : "r"(a0), "r"(a1), "r"(a2), "r"(a3), "r"(b0), "r"(b1));
}
__device__ __forceinline__ void ldsm4(uint32_t& r0, uint32_t& r1, uint32_t& r2, uint32_t& r3,
                                      uint32_t addr) {
    asm volatile("ldmatrix.sync.aligned.m8n8.x4.shared.b16 {%0,%1,%2,%3}, [%4];"
                 : "=r"(r0), "=r"(r1), "=r"(r2), "=r"(r3) : "r"(addr));
}

// ---------------- ncu-alignment no-op ----------------
__global__ void align_kernel() {}

// ---------------- prep: pack fp16 B-fragments (kt-paired, own-quarter-first k) ----------------
__device__ __forceinline__ float wval_g(const float* Wih, const float* Whh, const float* Wout,
                                        int q, int nt, int qrow, int kp) {
    int k = ((q + (kp >> 6)) & 3) * 64 + (kp & 63);
    if (nt < 32) {
        int col = nt * 8 + qrow;
        int hc  = q * 64 + (col >> 2);
        int g   = col & 3;
        if (g == 0) return Wih[hc*RDIM+k] + Whh[hc*RDIM+k];
        if (g == 1) return Wih[(256+hc)*RDIM+k] + Whh[(256+hc)*RDIM+k];
        if (g == 2) return Wih[(512+hc)*RDIM+k];
        return Whh[(512+hc)*RDIM+k];
    }
    int oc = q * 16 + (nt - 32) * 8 + qrow;
    return Wout[oc*RDIM + k];
}

__global__ void prep_kernel(const float* __restrict__ Wih,
                            const float* __restrict__ Whh,
                            const float* __restrict__ Wout,
                            const float* __restrict__ Wlh) {
    int i0 = blockIdx.x * blockDim.x + threadIdx.x;
    int stride = gridDim.x * blockDim.x;

    const int TOT = 4 * W_U4;     // uint4 count
    for (int idx = i0; idx < TOT; idx += stride) {
        int lane = idx & 31;
        int kt2  = (idx >> 5) & 7;
        int nt   = (idx >> 8) % NTILES;
        int q    = idx / (256 * NTILES);
        int qrow = lane >> 2;
        int c    = lane & 3;
        int ke   = (2 * kt2) * 16 + 2 * c;       // even ktile
        int ko   = (2 * kt2 + 1) * 16 + 2 * c;   // odd ktile
        float e00 = wval_g(Wih, Whh, Wout, q, nt, qrow, ke);
        float e01 = wval_g(Wih, Whh, Wout, q, nt, qrow, ke + 1);
        float e10 = wval_g(Wih, Whh, Wout, q, nt, qrow, ke + 8);
        float e11 = wval_g(Wih, Whh, Wout, q, nt, qrow, ke + 9);
        float o00 = wval_g(Wih, Whh, Wout, q, nt, qrow, ko);
        float o01 = wval_g(Wih, Whh, Wout, q, nt, qrow, ko + 1);
        float o10 = wval_g(Wih, Whh, Wout, q, nt, qrow, ko + 8);
        float o11 = wval_g(Wih, Whh, Wout, q, nt, qrow, ko + 9);
        uint4 v;
        v.x = (uint32_t)h_hi(e00) | ((uint32_t)h_hi(e01) << 16);
        v.y = (uint32_t)h_hi(e10) | ((uint32_t)h_hi(e11) << 16);
        v.z = (uint32_t)h_hi(o00) | ((uint32_t)h_hi(o01) << 16);
        v.w = (uint32_t)h_hi(o10) | ((uint32_t)h_hi(o11) << 16);
        g_bs[idx] = v;
    }
    for (int idx = i0; idx < RDIM * 768; idx += stride) {
        int k = idx / 768, row = idx % 768;
        g_WhhT[idx] = Whh[row * RDIM + k];
    }
    for (int idx = i0; idx < ZCD * RDIM; idx += stride) {
        int k = idx >> 8, c = idx & 255;
        g_WlhT[idx] = Wlh[c * ZCD + k];
    }
    for (int idx = i0; idx < 128; idx += stride)
        g_flag[idx] = 0;
}

// ---------------- pre-kernel (f32x2): exact fp32 h0 + step-0 GRU -> g_h1 ----------------
__global__ void __launch_bounds__(256)
pre_kernel(const float* __restrict__ z, const float* __restrict__ xc,
           const float* __restrict__ blh, const float* __restrict__ bih,
           const float* __restrict__ bhh) {
    __shared__ __align__(16) float zc_t[ZCD * 16];
    __shared__ __align__(16) float h0_t[RDIM * 18];
    const int tid  = threadIdx.x;
    const int row0 = blockIdx.x * 16;

    for (int i = tid; i < 16 * ZCD; i += 256) {
        int r = i & 15, k = i >> 4;
        float v = (k < HIDD) ? z[(row0 + r) * HIDD + k]
                             : xc[(row0 + r) * CONDD + (k - HIDD)];
        zc_t[k * 16 + r] = v;
    }
    __syncthreads();

    float2 acc[8];
    {
        float bv = blh[tid];
        #pragma unroll
        for (int rp = 0; rp < 8; ++rp) acc[rp] = make_float2(bv, bv);
        for (int k = 0; k < ZCD; ++k) {
            float w = g_WlhT[k * RDIM + tid];
            float2 w2 = make_float2(w, w);
            #pragma unroll
            for (int rp = 0; rp < 8; ++rp)
                acc[rp] = ffma2(*reinterpret_cast<const float2*>(&zc_t[k * 16 + 2 * rp]), w2, acc[rp]);
        }
        #pragma unroll
        for (int rp = 0; rp < 8; ++rp)
            *reinterpret_cast<float2*>(&h0_t[tid * 18 + 2 * rp]) = acc[rp];
    }
    __syncthreads();

    float2 aR[8], aU[8], aH[8];
    #pragma unroll
    for (int rp = 0; rp < 8; ++rp) {
        aR[rp] = make_float2(0.f, 0.f); aU[rp] = make_float2(0.f, 0.f); aH[rp] = make_float2(0.f, 0.f);
    }
    for (int k = 0; k < RDIM; ++k) {
        float wr = g_WhhT[k * 768 + tid];
        float wu = g_WhhT[k * 768 + 256 + tid];
        float wn = g_WhhT[k * 768 + 512 + tid];
        float2 wr2 = make_float2(wr, wr), wu2 = make_float2(wu, wu), wn2 = make_float2(wn, wn);
        #pragma unroll
        for (int rp = 0; rp < 8; ++rp) {
            float2 h2 = *reinterpret_cast<const float2*>(&h0_t[k * 18 + 2 * rp]);
            aR[rp] = ffma2(h2, wr2, aR[rp]);
            aU[rp] = ffma2(h2, wu2, aU[rp]);
            aH[rp] = ffma2(h2, wn2, aH[rp]);
        }
    }
    const float br = bih[tid] + bhh[tid];
    const float bu = bih[256 + tid] + bhh[256 + tid];
    const float bi = bih[512 + tid];
    const float bh = bhh[512 + tid];
    #pragma unroll
    for (int rp = 0; rp < 8; ++rp) {
        #pragma unroll
        for (int e = 0; e < 2; ++e) {
            int r = 2 * rp + e;
            float gr = e ? aR[rp].y : aR[rp].x;
            float gu = e ? aU[rp].y : aU[rp].x;
            float gh = e ? aH[rp].y : aH[rp].x;
            float rg = sigf(gr + br);
            float ug = sigf(gu + bu);
            float nn = tanhf(fmaf(rg, gh + bh, bi));
            float h0v = h0_t[tid * 18 + r];
            g_h1[(row0 + r) * RDIM + tid] = fmaf(ug, h0v - nn, nn);
        }
    }
}

// ---------------- gate epilogue per tile ----------------
__device__ __forceinline__ void gate_tile(const float* d4, int nt, int lane, int cc, int rowA,
                                          float* h_s, uint16_t* a_hi, uint16_t* a_lo,
                                          const float* bias, uint32_t* stg_w) {
    float e0 = __shfl_xor_sync(0xffffffffu, d4[0], 1);
    float e1 = __shfl_xor_sync(0xffffffffu, d4[1], 1);
    float e2 = __shfl_xor_sync(0xffffffffu, d4[2], 1);
    float e3 = __shfl_xor_sync(0xffffffffu, d4[3], 1);
    if (!(cc & 1)) {
        const int hc = nt * 2 + ((lane & 2) >> 1);
        float rg = sigf(d4[0] + bias[hc]);
        float ug = sigf(d4[1] + bias[64 + hc]);
        float nn = tanha(fmaf(rg, e1 + bias[192 + hc], e0 + bias[128 + hc]));
        float ho = h_s[rowA * 64 + hc];
        float hvA = fmaf(ug, ho - nn, nn);
        rg = sigf(d4[2] + bias[hc]);
        ug = sigf(d4[3] + bias[64 + hc]);
        nn = tanha(fmaf(rg, e3 + bias[192 + hc], e2 + bias[128 + hc]));
        ho = h_s[(rowA + 8) * 64 + hc];
        float hvB = fmaf(ug, ho - nn, nn);

        h_s[rowA * 64 + hc]       = hvA;
        h_s[(rowA + 8) * 64 + hc] = hvB;
        uint16_t hA = h_hi(hvA), lA = h_lo(hvA);
        uint16_t hB = h_hi(hvB), lB = h_lo(hvB);
        a_hi[rowA * APITCH + hc]       = hA;
        a_lo[rowA * APITCH + hc]       = lA;
        a_hi[(rowA + 8) * APITCH + hc] = hB;
        a_lo[(rowA + 8) * APITCH + hc] = lB;
        __stcg(&stg_w[rowA * 64 + hc],       (uint32_t)hA | ((uint32_t)lA << 16));
        __stcg(&stg_w[(rowA + 8) * 64 + hc], (uint32_t)hB | ((uint32_t)lB << 16));
    }
}

// ---------------- main persistent 4-way-split kernel ----------------
__global__ void __launch_bounds__(NT, 1)
gru_main_kernel(const float* __restrict__ bih, const float* __restrict__ bhh,
                const float* __restrict__ bout, float* __restrict__ out) {
    extern __shared__ __align__(16) char smem[];
    uint4*    w_s  = reinterpret_cast<uint4*>(smem + OFF_W);
    uint16_t* a_hi = reinterpret_cast<uint16_t*>(smem + OFF_AHI);
    uint16_t* a_lo = reinterpret_cast<uint16_t*>(smem + OFF_ALO);
    float*    h_s  = reinterpret_cast<float*>(smem + OFF_HS);
    float*    bias = reinterpret_cast<float*>(smem + OFF_BIAS);

    const int tid  = threadIdx.x;
    const int wid  = tid >> 5;
    const int lane = tid & 31;
    const int cc   = lane & 3;
    const int gID  = lane >> 2;
    const int m    = blockIdx.x >> 2;
    const int q    = blockIdx.x & 3;
    const int row0 = m * MROWS;
    const int mt   = wid & 3;
    const int g    = wid >> 2;
    const int rowA = mt * 16 + gID;
    const int ntbase = (g < 2) ? g * 9 : 18 + (g - 2) * 8;
    const bool has9  = (g < 2);

    // ---- resident weights: one-time 136KB copy ----
    {
        const uint4* wg4 = g_bs + (size_t)q * W_U4;
        for (int i = tid; i < W_U4; i += NT) w_s[i] = wg4[i];
    }
    if (tid < 64) {
        int H = q * 64 + tid;
        bias[tid]       = bih[H] + bhh[H];
        bias[64 + tid]  = bih[256 + H] + bhh[256 + H];
        bias[128 + tid] = bih[512 + H];
        bias[192 + tid] = bhh[512 + H];
    }
    if (tid < 16) bias[256 + tid] = bout[q * 16 + tid];

    // A planes in permuted column order
    for (int i = tid; i < MROWS * RDIM; i += NT) {
        int r = i >> 8, kp = i & 255;
        int k = ((q + (kp >> 6)) & 3) * 64 + (kp & 63);
        float v = g_h1[(row0 + r) * RDIM + k];
        a_hi[r * APITCH + kp] = h_hi(v);
        a_lo[r * APITCH + kp] = h_lo(v);
    }
    for (int i = tid; i < MROWS * 64; i += NT) {
        int r = i >> 6, c = i & 63;
        h_s[i] = g_h1[(row0 + r) * RDIM + q * 64 + c];
    }
    __syncthreads();

    // ldmatrix per-lane address bases (row = mt*16 + (lane&7) + (lane&8), k-half by lane>>4)
    const int ldrow = mt * 16 + (lane & 7) + (lane & 8);
    const uint32_t loff = (uint32_t)(ldrow * APITCH + ((lane >> 4) << 3)) * 2u;
    const uint32_t ahi_u = smem_u32(a_hi) + loff;
    const uint32_t alo_u = smem_u32(a_lo) + loff;

    int* my_flag = &g_flag[m * 4 + q];

    #pragma unroll 1
    for (int j = 1; j <= MAXLEN; ++j) {
        float d[9][4];
        #pragma unroll
        for (int n = 0; n < 9; ++n) { d[n][0]=0.f; d[n][1]=0.f; d[n][2]=0.f; d[n][3]=0.f; }

        // ---- K phase 1: kt-pairs 0-1 (OWN quarter) ----
        #pragma unroll
        for (int kt2 = 0; kt2 < 2; ++kt2) {
            uint32_t he[4], ho[4], le[4], lo4[4];
            ldsm4(he[0], he[1], he[2], he[3], ahi_u + (2 * kt2) * 32u);
            ldsm4(le[0], le[1], le[2], le[3], alo_u + (2 * kt2) * 32u);
            ldsm4(ho[0], ho[1], ho[2], ho[3], ahi_u + (2 * kt2 + 1) * 32u);
            ldsm4(lo4[0], lo4[1], lo4[2], lo4[3], alo_u + (2 * kt2 + 1) * 32u);
            #pragma unroll
            for (int n = 0; n < 9; ++n) {
                if (n == 8 && !has9) break;
                uint4 B = w_s[((ntbase + n) * 8 + kt2) * 32 + lane];
                mma16816(d[n], he[0], he[1], he[2], he[3], B.x, B.y);
                mma16816(d[n], le[0], le[1], le[2], le[3], B.x, B.y);
                mma16816(d[n], ho[0], ho[1], ho[2], ho[3], B.z, B.w);
                mma16816(d[n], lo4[0], lo4[1], lo4[2], lo4[3], B.z, B.w);
            }
        }

        // ---- install 3 peers' h_j into A cols [64,256) ----
        if (j >= 2) {
            if (lane == 0) {
                #pragma unroll
                for (int dq = 1; dq < 4; ++dq) {
                    const int pq = (q + dq) & 3;
                    while (flag_acquire(&g_flag[m * 4 + pq]) < j - 1) { }
                }
            }
            __syncwarp();
            #pragma unroll
            for (int dq = 1; dq < 4; ++dq) {
                const int pq = (q + dq) & 3;
                const uint4* stg_r = reinterpret_cast<const uint4*>(
                    g_stage + (((size_t)(m * 4 + pq) * 2 + ((j - 1) & 1)) << 12));
                #pragma unroll
                for (int i = 0; i < 2; ++i) {
                    int idx = tid + i * NT;
                    uint4 v = __ldcg(&stg_r[idx]);
                    int r = idx >> 4, c4 = (idx & 15) * 4;
                    uint16_t* ph = a_hi + r * APITCH + dq * 64 + c4;
                    uint16_t* pl = a_lo + r * APITCH + dq * 64 + c4;
                    ph[0] = (uint16_t)(v.x & 0xffffu); pl[0] = (uint16_t)(v.x >> 16);
                    ph[1] = (uint16_t)(v.y & 0xffffu); pl[1] = (uint16_t)(v.y >> 16);
                    ph[2] = (uint16_t)(v.z & 0xffffu); pl[2] = (uint16_t)(v.z >> 16);
                    ph[3] = (uint16_t)(v.w & 0xffffu); pl[3] = (uint16_t)(v.w >> 16);
                }
            }
        }
        __syncthreads();

        // ---- K phase 2: kt-pairs 2-7 (peer quarters) ----
        #pragma unroll
        for (int kt2 = 2; kt2 < 8; ++kt2) {
            uint32_t he[4], ho[4], le[4], lo4[4];
            ldsm4(he[0], he[1], he[2], he[3], ahi_u + (2 * kt2) * 32u);
            ldsm4(le[0], le[1], le[2], le[3], alo_u + (2 * kt2) * 32u);
            ldsm4(ho[0], ho[1], ho[2], ho[3], ahi_u + (2 * kt2 + 1) * 32u);
            ldsm4(lo4[0], lo4[1], lo4[2], lo4[3], alo_u + (2 * kt2 + 1) * 32u);
            #pragma unroll
            for (int n = 0; n < 9; ++n) {
                if (n == 8 && !has9) break;
                uint4 B = w_s[((ntbase + n) * 8 + kt2) * 32 + lane];
                mma16816(d[n], he[0], he[1], he[2], he[3], B.x, B.y);
                mma16816(d[n], le[0], le[1], le[2], le[3], B.x, B.y);
                mma16816(d[n], ho[0], ho[1], ho[2], ho[3], B.z, B.w);
                mma16816(d[n], lo4[0], lo4[1], lo4[2], lo4[3], B.z, B.w);
            }
        }

        // ---- epilogue ----
        uint32_t* stg_w = g_stage + (((size_t)(m * 4 + q) * 2 + (j & 1)) << 12);
        const int ncnt = has9 ? 9 : 8;
        #pragma unroll
        for (int n = 0; n < 9; ++n) {
            if (n >= ncnt) break;
            const int nt = ntbase + n;
            if (nt < 32) {
                if (j < MAXLEN)
                    gate_tile(d[n], nt, lane, cc, rowA, h_s, a_hi, a_lo, bias, stg_w);
            } else {
                const int loc = (nt - 32) * 8 + 2 * cc;
                const int oc  = q * 16 + loc;
                const size_t o0 = ((size_t)(row0 + rowA) * MAXLEN + (j - 1)) * NCHD + oc;
                const size_t o8 = o0 + (size_t)8 * MAXLEN * NCHD;
                out[o0]     = d[n][0] + bias[256 + loc];
                out[o0 + 1] = d[n][1] + bias[256 + loc + 1];
                out[o8]     = d[n][2] + bias[256 + loc];
                out[o8 + 1] = d[n][3] + bias[256 + loc + 1];
            }
        }
        __syncthreads();
        if (j < MAXLEN && tid == 0)
            flag_release(my_flag, j);
    }
}

// ---------------- launcher ----------------
extern "C" void kernel_launch(void* const* d_in, const int* in_sizes, int n_in,
                              void* d_out, int out_size) {
    const float* z     = (const float*)d_in[0];
    const float* xcond = (const float*)d_in[1];
    const float* W_lh  = (const float*)d_in[2];
    const float* b_lh  = (const float*)d_in[3];
    const float* W_ih  = (const float*)d_in[4];
    const float* W_hh  = (const float*)d_in[5];
    const float* b_ih  = (const float*)d_in[6];
    const float* b_hh  = (const float*)d_in[7];
    const float* W_out = (const float*)d_in[8];
    const float* b_out = (const float*)d_in[9];
    float* out = (float*)d_out;

    cudaFuncSetAttribute(gru_main_kernel, cudaFuncAttributeMaxDynamicSharedMemorySize, SMEM_DYN);

    align_kernel<<<1, 32>>>();   // shifts ncu -s 5 capture onto gru_main_kernel
    prep_kernel<<<256, 256>>>(W_ih, W_hh, W_out, W_lh);
    pre_kernel<<<128, 256>>>(z, xcond, b_lh, b_ih, b_hh);
    gru_main_kernel<<<NBLK, NT, SMEM_DYN>>>(b_ih, b_hh, b_out, out);
}

// round 13
// speedup vs baseline: 1.3103x; 1.3103x over previous
#include <cuda_runtime.h>
#include <cuda_fp16.h>
#include <cstdint>

// ---------------- problem constants ----------------
#define BATCH   2048
#define RDIM    256
#define HIDD    256
#define CONDD   128
#define ZCD     384
#define NCHD    64
#define MAXLEN  128
#define NBLK    128            // 32 M-tiles x 4 N-quarters
#define NT      512            // 16 warps: (4 m-tiles) x (4 n-groups)
#define MROWS   64             // batch rows per CTA (quartet shares them)
#define NTILES  34             // n8 tiles per CTA: 32 gate (paired) + 2 logit
#define KTILES  16
#define APITCH  264            // u16 pitch of A planes (conflict-free)

#define W_U2    (KTILES*NTILES*32)     // 17408 uint2 = 139264 B
// dynamic smem layout (bytes)
#define OFF_W    0
#define OFF_AHI  139264
#define OFF_ALO  (OFF_AHI + MROWS*APITCH*2)   // +33792
#define OFF_HS   (OFF_ALO + MROWS*APITCH*2)   // +33792
#define OFF_BIAS (OFF_HS + MROWS*64*4)        // +16384
#define SMEM_DYN (OFF_BIAS + 1536)            // 224768

// ---------------- device-global scratch ----------------
__device__ __align__(16) uint2 g_bs[4 * W_U2];            // per-quarter W fragments (permuted k, paired gates)
__device__ float    g_h1[BATCH * RDIM];
__device__ uint32_t g_stage[32 * 4 * 2 * (MROWS * 64)];    // [m][q][parity][row*64+hc] = 4MB
__device__ int      g_flag[128];
__device__ float    g_WhhT[RDIM * 768];
__device__ float    g_WlhT[ZCD * RDIM];

// ---------------- helpers ----------------
__device__ __forceinline__ float sigf(float x) { return 1.0f / (1.0f + __expf(-x)); }
__device__ __forceinline__ float tanha(float x) {
    float y; asm("tanh.approx.f32 %0, %1;" : "=f"(y) : "f"(x)); return y;
}
__device__ __forceinline__ uint16_t h_hi(float x) {
    __half h = __float2half_rn(x); return __half_as_ushort(h);
}
__device__ __forceinline__ uint16_t h_lo(float x) {
    __half h = __float2half_rn(x);
    return __half_as_ushort(__float2half_rn(x - __half2float(h)));
}
__device__ __forceinline__ void flag_release(int* p, int v) {
    asm volatile("st.release.gpu.s32 [%0], %1;" :: "l"(p), "r"(v) : "memory");
}
__device__ __forceinline__ int flag_acquire(const int* p) {
    int v; asm volatile("ld.acquire.gpu.s32 %0, [%1];" : "=r"(v) : "l"(p) : "memory");
    return v;
}
__device__ __forceinline__ float2 ffma2(float2 a, float2 b, float2 c) {
    unsigned long long au = *reinterpret_cast<unsigned long long*>(&a);
    unsigned long long bu = *reinterpret_cast<unsigned long long*>(&b);
    unsigned long long cu = *reinterpret_cast<unsigned long long*>(&c);
    unsigned long long du;
    asm("fma.rn.f32x2 %0, %1, %2, %3;" : "=l"(du) : "l"(au), "l"(bu), "l"(cu));
    return *reinterpret_cast<float2*>(&du);
}
__device__ __forceinline__ void mma16816(float* d, uint32_t a0, uint32_t a1, uint32_t a2, uint32_t a3,
                                         uint32_t b0, uint32_t b1) {
    asm volatile(
        "mma.sync.aligned.m16n8k16.row.col.f32.f16.f16.f32 "
        "{%0,%1,%2,%3}, {%4,%5,%6,%7}, {%8,%9}, {%0,%1,%2,%3};"
        : "+f"(d[0]), "+f"(d[1]), "+f"(d[2]), "+f"(d[3])
        : "r"(a0), "r"(a1), "r"(a2), "r"(a3), "r"(b0), "r"(b1));
}

// ---------------- ncu-alignment no-op ----------------
__global__ void align_kernel() {}

// ---------------- prep: pack fp16 B-fragments (paired-gate cols, own-quarter-first k) ----------------
// Gate ntile pairing: tile 2p cols = [hc0*r, hc0*u, hc1*r, hc1*u, hc2*r, hc2*u, hc3*r, hc3*u]
//                     tile 2p+1    = same hcols with gates (i_n, h_n); hc_i = p*4+i (own-local).
__device__ __forceinline__ float wval_g(const float* Wih, const float* Whh, const float* Wout,
                                        int q, int nt, int qrow, int kp) {
    int k = ((q + (kp >> 6)) & 3) * 64 + (kp & 63);
    if (nt < 32) {
        int p    = nt >> 1;
        int half = nt & 1;
        int H    = q * 64 + p * 4 + (qrow >> 1);
        int gsel = half * 2 + (qrow & 1);     // 0=r, 1=u, 2=i_n, 3=h_n
        if (gsel == 0) return Wih[H*RDIM+k] + Whh[H*RDIM+k];
        if (gsel == 1) return Wih[(256+H)*RDIM+k] + Whh[(256+H)*RDIM+k];
        if (gsel == 2) return Wih[(512+H)*RDIM+k];
        return Whh[(512+H)*RDIM+k];
    }
    int oc = q * 16 + (nt - 32) * 8 + qrow;
    return Wout[oc*RDIM + k];
}

__global__ void prep_kernel(const float* __restrict__ Wih,
                            const float* __restrict__ Whh,
                            const float* __restrict__ Wout,
                            const float* __restrict__ Wlh) {
    int i0 = blockIdx.x * blockDim.x + threadIdx.x;
    int stride = gridDim.x * blockDim.x;

    const int TOT = 4 * W_U2;
    for (int idx = i0; idx < TOT; idx += stride) {
        int lane = idx & 31;
        int nt   = (idx >> 5) % NTILES;
        int kt   = (idx / (32 * NTILES)) % KTILES;
        int q    = idx / (32 * NTILES * KTILES);
        int qrow = lane >> 2;
        int c    = lane & 3;
        int k0   = kt * 16 + 2 * c;
        float w00 = wval_g(Wih, Whh, Wout, q, nt, qrow, k0);
        float w01 = wval_g(Wih, Whh, Wout, q, nt, qrow, k0 + 1);
        float w10 = wval_g(Wih, Whh, Wout, q, nt, qrow, k0 + 8);
        float w11 = wval_g(Wih, Whh, Wout, q, nt, qrow, k0 + 9);
        uint2 o;
        o.x = (uint32_t)h_hi(w00) | ((uint32_t)h_hi(w01) << 16);
        o.y = (uint32_t)h_hi(w10) | ((uint32_t)h_hi(w11) << 16);
        g_bs[idx] = o;
    }
    for (int idx = i0; idx < RDIM * 768; idx += stride) {
        int k = idx / 768, row = idx % 768;
        g_WhhT[idx] = Whh[row * RDIM + k];
    }
    for (int idx = i0; idx < ZCD * RDIM; idx += stride) {
        int k = idx >> 8, c = idx & 255;
        g_WlhT[idx] = Wlh[c * ZCD + k];
    }
    for (int idx = i0; idx < 128; idx += stride)
        g_flag[idx] = 0;
}

// ---------------- pre-kernel (f32x2): exact fp32 h0 + step-0 GRU -> g_h1 ----------------
__global__ void __launch_bounds__(256)
pre_kernel(const float* __restrict__ z, const float* __restrict__ xc,
           const float* __restrict__ blh, const float* __restrict__ bih,
           const float* __restrict__ bhh) {
    __shared__ __align__(16) float zc_t[ZCD * 16];
    __shared__ __align__(16) float h0_t[RDIM * 18];
    const int tid  = threadIdx.x;
    const int row0 = blockIdx.x * 16;

    for (int i = tid; i < 16 * ZCD; i += 256) {
        int r = i & 15, k = i >> 4;
        float v = (k < HIDD) ? z[(row0 + r) * HIDD + k]
                             : xc[(row0 + r) * CONDD + (k - HIDD)];
        zc_t[k * 16 + r] = v;
    }
    __syncthreads();

    float2 acc[8];
    {
        float bv = blh[tid];
        #pragma unroll
        for (int rp = 0; rp < 8; ++rp) acc[rp] = make_float2(bv, bv);
        for (int k = 0; k < ZCD; ++k) {
            float w = g_WlhT[k * RDIM + tid];
            float2 w2 = make_float2(w, w);
            #pragma unroll
            for (int rp = 0; rp < 8; ++rp)
                acc[rp] = ffma2(*reinterpret_cast<const float2*>(&zc_t[k * 16 + 2 * rp]), w2, acc[rp]);
        }
        #pragma unroll
        for (int rp = 0; rp < 8; ++rp)
            *reinterpret_cast<float2*>(&h0_t[tid * 18 + 2 * rp]) = acc[rp];
    }
    __syncthreads();

    float2 aR[8], aU[8], aH[8];
    #pragma unroll
    for (int rp = 0; rp < 8; ++rp) {
        aR[rp] = make_float2(0.f, 0.f); aU[rp] = make_float2(0.f, 0.f); aH[rp] = make_float2(0.f, 0.f);
    }
    for (int k = 0; k < RDIM; ++k) {
        float wr = g_WhhT[k * 768 + tid];
        float wu = g_WhhT[k * 768 + 256 + tid];
        float wn = g_WhhT[k * 768 + 512 + tid];
        float2 wr2 = make_float2(wr, wr), wu2 = make_float2(wu, wu), wn2 = make_float2(wn, wn);
        #pragma unroll
        for (int rp = 0; rp < 8; ++rp) {
            float2 h2 = *reinterpret_cast<const float2*>(&h0_t[k * 18 + 2 * rp]);
            aR[rp] = ffma2(h2, wr2, aR[rp]);
            aU[rp] = ffma2(h2, wu2, aU[rp]);
            aH[rp] = ffma2(h2, wn2, aH[rp]);
        }
    }
    const float br = bih[tid] + bhh[tid];
    const float bu = bih[256 + tid] + bhh[256 + tid];
    const float bi = bih[512 + tid];
    const float bh = bhh[512 + tid];
    #pragma unroll
    for (int rp = 0; rp < 8; ++rp) {
        #pragma unroll
        for (int e = 0; e < 2; ++e) {
            int r = 2 * rp + e;
            float gr = e ? aR[rp].y : aR[rp].x;
            float gu = e ? aU[rp].y : aU[rp].x;
            float gh = e ? aH[rp].y : aH[rp].x;
            float rg = sigf(gr + br);
            float ug = sigf(gu + bu);
            float nn = tanhf(fmaf(rg, gh + bh, bi));
            float h0v = h0_t[tid * 18 + r];
            g_h1[(row0 + r) * RDIM + tid] = fmaf(ug, h0v - nn, nn);
        }
    }
}

// ---------------- main persistent 4-way-split kernel ----------------
__global__ void __launch_bounds__(NT, 1)
gru_main_kernel(const float* __restrict__ bih, const float* __restrict__ bhh,
                const float* __restrict__ bout, float* __restrict__ out) {
    extern __shared__ __align__(16) char smem[];
    uint2*    w_s  = reinterpret_cast<uint2*>(smem + OFF_W);
    uint16_t* a_hi = reinterpret_cast<uint16_t*>(smem + OFF_AHI);
    uint16_t* a_lo = reinterpret_cast<uint16_t*>(smem + OFF_ALO);
    float*    h_s  = reinterpret_cast<float*>(smem + OFF_HS);
    float*    bias = reinterpret_cast<float*>(smem + OFF_BIAS);

    const int tid  = threadIdx.x;
    const int wid  = tid >> 5;
    const int lane = tid & 31;
    const int cc   = lane & 3;
    const int gID  = lane >> 2;
    const int m    = blockIdx.x >> 2;
    const int q    = blockIdx.x & 3;
    const int row0 = m * MROWS;
    const int mt   = wid & 3;            // m16 tile
    const int g    = wid >> 2;           // n-group: gate tiles [8g, 8g+8), +logit tile 32+g for g<2
    const int rowA = mt * 16 + gID;
    const bool haslog = (g < 2);

    // ---- resident weights: one-time 136KB copy ----
    {
        const uint4* wg4 = reinterpret_cast<const uint4*>(g_bs + (size_t)q * W_U2);
        uint4* ws4 = reinterpret_cast<uint4*>(w_s);
        for (int i = tid; i < W_U2 / 2; i += NT) ws4[i] = wg4[i];
    }
    if (tid < 64) {
        int H = q * 64 + tid;
        bias[tid]       = bih[H] + bhh[H];
        bias[64 + tid]  = bih[256 + H] + bhh[256 + H];
        bias[128 + tid] = bih[512 + H];
        bias[192 + tid] = bhh[512 + H];
    }
    if (tid < 16) bias[256 + tid] = bout[q * 16 + tid];

    // A planes in permuted column order
    for (int i = tid; i < MROWS * RDIM; i += NT) {
        int r = i >> 8, kp = i & 255;
        int k = ((q + (kp >> 6)) & 3) * 64 + (kp & 63);
        float v = g_h1[(row0 + r) * RDIM + k];
        a_hi[r * APITCH + kp] = h_hi(v);
        a_lo[r * APITCH + kp] = h_lo(v);
    }
    for (int i = tid; i < MROWS * 64; i += NT) {
        int r = i >> 6, c = i & 63;
        h_s[i] = g_h1[(row0 + r) * RDIM + q * 64 + c];
    }
    __syncthreads();

    int* my_flag = &g_flag[m * 4 + q];

    #pragma unroll 1
    for (int j = 1; j <= MAXLEN; ++j) {
        float d[9][4];
        #pragma unroll
        for (int n = 0; n < 9; ++n) { d[n][0]=0.f; d[n][1]=0.f; d[n][2]=0.f; d[n][3]=0.f; }

        // ---- K phase 1: ktiles 0-3 (OWN quarter, locally fresh) ----
        #pragma unroll
        for (int kt = 0; kt < 4; ++kt) {
            const int k0 = kt * 16 + 2 * cc;
            uint32_t ah0 = *reinterpret_cast<const uint32_t*>(a_hi + rowA * APITCH + k0);
            uint32_t ah1 = *reinterpret_cast<const uint32_t*>(a_hi + (rowA + 8) * APITCH + k0);
            uint32_t ah2 = *reinterpret_cast<const uint32_t*>(a_hi + rowA * APITCH + k0 + 8);
            uint32_t ah3 = *reinterpret_cast<const uint32_t*>(a_hi + (rowA + 8) * APITCH + k0 + 8);
            uint32_t al0 = *reinterpret_cast<const uint32_t*>(a_lo + rowA * APITCH + k0);
            uint32_t al1 = *reinterpret_cast<const uint32_t*>(a_lo + (rowA + 8) * APITCH + k0);
            uint32_t al2 = *reinterpret_cast<const uint32_t*>(a_lo + rowA * APITCH + k0 + 8);
            uint32_t al3 = *reinterpret_cast<const uint32_t*>(a_lo + (rowA + 8) * APITCH + k0 + 8);
            #pragma unroll
            for (int n = 0; n < 9; ++n) {
                if (n == 8 && !haslog) break;
                const int nt = (n < 8) ? (8 * g + n) : (32 + g);
                uint2 B = w_s[(kt * NTILES + nt) * 32 + lane];
                mma16816(d[n], ah0, ah1, ah2, ah3, B.x, B.y);
                mma16816(d[n], al0, al1, al2, al3, B.x, B.y);
            }
        }

        // ---- install 3 peers' h_j into A cols [64,256) (disjoint from phase-1 reads) ----
        if (j >= 2) {
            if (lane == 0) {
                #pragma unroll
                for (int dq = 1; dq < 4; ++dq) {
                    const int pq = (q + dq) & 3;
                    while (flag_acquire(&g_flag[m * 4 + pq]) < j - 1) { }
                }
            }
            __syncwarp();
            #pragma unroll
            for (int dq = 1; dq < 4; ++dq) {
                const int pq = (q + dq) & 3;
                const uint4* stg_r = reinterpret_cast<const uint4*>(
                    g_stage + (((size_t)(m * 4 + pq) * 2 + ((j - 1) & 1)) << 12));
                #pragma unroll
                for (int i = 0; i < 2; ++i) {
                    int idx = tid + i * NT;
                    uint4 v = __ldcg(&stg_r[idx]);
                    int r = idx >> 4, c4 = (idx & 15) * 4;
                    uint16_t* ph = a_hi + r * APITCH + dq * 64 + c4;
                    uint16_t* pl = a_lo + r * APITCH + dq * 64 + c4;
                    ph[0] = (uint16_t)(v.x & 0xffffu); pl[0] = (uint16_t)(v.x >> 16);
                    ph[1] = (uint16_t)(v.y & 0xffffu); pl[1] = (uint16_t)(v.y >> 16);
                    ph[2] = (uint16_t)(v.z & 0xffffu); pl[2] = (uint16_t)(v.z >> 16);
                    ph[3] = (uint16_t)(v.w & 0xffffu); pl[3] = (uint16_t)(v.w >> 16);
                }
            }
        }
        __syncthreads();   // installs visible to all warps

        // ---- K phase 2: ktiles 4-15 (peer quarters) ----
        #pragma unroll
        for (int kt = 4; kt < 16; ++kt) {
            const int k0 = kt * 16 + 2 * cc;
            uint32_t ah0 = *reinterpret_cast<const uint32_t*>(a_hi + rowA * APITCH + k0);
            uint32_t ah1 = *reinterpret_cast<const uint32_t*>(a_hi + (rowA + 8) * APITCH + k0);
            uint32_t ah2 = *reinterpret_cast<const uint32_t*>(a_hi + rowA * APITCH + k0 + 8);
            uint32_t ah3 = *reinterpret_cast<const uint32_t*>(a_hi + (rowA + 8) * APITCH + k0 + 8);
            uint32_t al0 = *reinterpret_cast<const uint32_t*>(a_lo + rowA * APITCH + k0);
            uint32_t al1 = *reinterpret_cast<const uint32_t*>(a_lo + (rowA + 8) * APITCH + k0);
            uint32_t al2 = *reinterpret_cast<const uint32_t*>(a_lo + rowA * APITCH + k0 + 8);
            uint32_t al3 = *reinterpret_cast<const uint32_t*>(a_lo + (rowA + 8) * APITCH + k0 + 8);
            #pragma unroll
            for (int n = 0; n < 9; ++n) {
                if (n == 8 && !haslog) break;
                const int nt = (n < 8) ? (8 * g + n) : (32 + g);
                uint2 B = w_s[(kt * NTILES + nt) * 32 + lane];
                mma16816(d[n], ah0, ah1, ah2, ah3, B.x, B.y);
                mma16816(d[n], al0, al1, al2, al3, B.x, B.y);
            }
        }

        // ---- epilogue: shfl-free, all lanes active ----
        uint32_t* stg_w = g_stage + (((size_t)(m * 4 + q) * 2 + (j & 1)) << 12);
        if (j < MAXLEN) {
            #pragma unroll
            for (int n = 0; n < 8; n += 2) {
                const int hc = (4 * g + (n >> 1)) * 4 + cc;   // own-local hcol, per-lane
                // row rowA: d[n] = (r,u), d[n+1] = (i_n,h_n)
                float rg = sigf(d[n][0] + bias[hc]);
                float ug = sigf(d[n][1] + bias[64 + hc]);
                float nn = tanha(fmaf(rg, d[n+1][1] + bias[192 + hc], d[n+1][0] + bias[128 + hc]));
                float ho = h_s[rowA * 64 + hc];
                float hvA = fmaf(ug, ho - nn, nn);
                // row rowA + 8
                rg = sigf(d[n][2] + bias[hc]);
                ug = sigf(d[n][3] + bias[64 + hc]);
                nn = tanha(fmaf(rg, d[n+1][3] + bias[192 + hc], d[n+1][2] + bias[128 + hc]));
                ho = h_s[(rowA + 8) * 64 + hc];
                float hvB = fmaf(ug, ho - nn, nn);

                h_s[rowA * 64 + hc]       = hvA;
                h_s[(rowA + 8) * 64 + hc] = hvB;
                uint16_t hA = h_hi(hvA), lA = h_lo(hvA);
                uint16_t hB = h_hi(hvB), lB = h_lo(hvB);
                a_hi[rowA * APITCH + hc]       = hA;   // own quarter = cols [0,64)
                a_lo[rowA * APITCH + hc]       = lA;
                a_hi[(rowA + 8) * APITCH + hc] = hB;
                a_lo[(rowA + 8) * APITCH + hc] = lB;
                __stcg(&stg_w[rowA * 64 + hc],       (uint32_t)hA | ((uint32_t)lA << 16));
                __stcg(&stg_w[(rowA + 8) * 64 + hc], (uint32_t)hB | ((uint32_t)lB << 16));
            }
        }
        if (haslog) {
            const int loc = g * 8 + 2 * cc;
            const int oc  = q * 16 + loc;
            const size_t o0 = ((size_t)(row0 + rowA) * MAXLEN + (j - 1)) * NCHD + oc;
            const size_t o8 = o0 + (size_t)8 * MAXLEN * NCHD;
            out[o0]     = d[8][0] + bias[256 + loc];
            out[o0 + 1] = d[8][1] + bias[256 + loc + 1];
            out[o8]     = d[8][2] + bias[256 + loc];
            out[o8 + 1] = d[8][3] + bias[256 + loc + 1];
        }
        __syncthreads();                 // own A cols + staging complete
        if (j < MAXLEN && tid == 0)
            flag_release(my_flag, j);
    }
}

// ---------------- launcher ----------------
extern "C" void kernel_launch(void* const* d_in, const int* in_sizes, int n_in,
                              void* d_out, int out_size) {
    const float* z     = (const float*)d_in[0];
    const float* xcond = (const float*)d_in[1];
    const float* W_lh  = (const float*)d_in[2];
    const float* b_lh  = (const float*)d_in[3];
    const float* W_ih  = (const float*)d_in[4];
    const float* W_hh  = (const float*)d_in[5];
    const float* b_ih  = (const float*)d_in[6];
    const float* b_hh  = (const float*)d_in[7];
    const float* W_out = (const float*)d_in[8];
    const float* b_out = (const float*)d_in[9];
    float* out = (float*)d_out;

    cudaFuncSetAttribute(gru_main_kernel, cudaFuncAttributeMaxDynamicSharedMemorySize, SMEM_DYN);

    align_kernel<<<1, 32>>>();   // keeps ncu -s 5 capture on gru_main_kernel
    prep_kernel<<<256, 256>>>(W_ih, W_hh, W_out, W_lh);
    pre_kernel<<<128, 256>>>(z, xcond, b_lh, b_ih, b_hh);
    gru_main_kernel<<<NBLK, NT, SMEM_DYN>>>(b_ih, b_hh, b_out, out);
}